// round 2
// baseline (speedup 1.0000x reference)
#include <cuda_runtime.h>
#include <math.h>
#include <stdint.h>

// Problem constants (4096 x 4096 fp32 images, 7x7 SSIM window)
#define W    4096
#define H    4096
#define OUTW 4090   // W - 6 (VALID 7x7)
#define OUTH 4090
#define TW   256    // output columns per block (ssim kernel)
#define RH   128    // output rows per block

// ---------------- device scratch (no allocations allowed) ----------------
__device__ double g_mse_sum;
__device__ double g_ssim_sum;
__device__ float  g_min;
__device__ float  g_max;

__global__ void init_kernel() {
    g_mse_sum  = 0.0;
    g_ssim_sum = 0.0;
    g_min = __int_as_float(0x7f800000);   // +inf
    g_max = __int_as_float(0xff800000);   // -inf
}

// Sign-aware float atomic min/max via int/uint monotone encodings.
__device__ __forceinline__ void atomicMaxF(float* a, float v) {
    if (v >= 0.f) atomicMax((int*)a, __float_as_int(v));
    else          atomicMin((unsigned int*)a, __float_as_uint(v));
}
__device__ __forceinline__ void atomicMinF(float* a, float v) {
    if (v >= 0.f) atomicMin((int*)a, __float_as_int(v));
    else          atomicMax((unsigned int*)a, __float_as_uint(v));
}

// ---------------- pass 1: mse sum + min/max of pred ----------------
__global__ __launch_bounds__(256) void reduce_kernel(
    const float4* __restrict__ pred, const float4* __restrict__ gt, int n4)
{
    float mse = 0.f;
    float mn  = __int_as_float(0x7f800000);
    float mx  = __int_as_float(0xff800000);

    for (int i = blockIdx.x * blockDim.x + threadIdx.x; i < n4;
         i += gridDim.x * blockDim.x) {
        float4 p = pred[i];
        float4 g = gt[i];
        float d0 = p.x - g.x, d1 = p.y - g.y, d2 = p.z - g.z, d3 = p.w - g.w;
        mse = fmaf(d0, d0, mse);
        mse = fmaf(d1, d1, mse);
        mse = fmaf(d2, d2, mse);
        mse = fmaf(d3, d3, mse);
        mn = fminf(mn, fminf(fminf(p.x, p.y), fminf(p.z, p.w)));
        mx = fmaxf(mx, fmaxf(fmaxf(p.x, p.y), fmaxf(p.z, p.w)));
    }

    // warp reduce
    #pragma unroll
    for (int o = 16; o > 0; o >>= 1) {
        mse += __shfl_down_sync(0xffffffffu, mse, o);
        mn = fminf(mn, __shfl_down_sync(0xffffffffu, mn, o));
        mx = fmaxf(mx, __shfl_down_sync(0xffffffffu, mx, o));
    }
    __shared__ float smse[8], smn[8], smx[8];
    int lane = threadIdx.x & 31, wid = threadIdx.x >> 5;
    if (lane == 0) { smse[wid] = mse; smn[wid] = mn; smx[wid] = mx; }
    __syncthreads();
    if (threadIdx.x < 8) {
        float a = smse[threadIdx.x];
        float b = smn[threadIdx.x];
        float c = smx[threadIdx.x];
        #pragma unroll
        for (int o = 4; o > 0; o >>= 1) {
            a += __shfl_down_sync(0xffu, a, o);
            b = fminf(b, __shfl_down_sync(0xffu, b, o));
            c = fmaxf(c, __shfl_down_sync(0xffu, c, o));
        }
        if (threadIdx.x == 0) {
            atomicAdd(&g_mse_sum, (double)a);
            atomicMinF(&g_min, b);
            atomicMaxF(&g_max, c);
        }
    }
}

// ---------------- pass 2: SSIM map sum ----------------
// Rescaled formula (multiply through by 49^2 = 2401); all window SUMS, no
// per-window normalization.  cn = 49/48 (sample covariance factor).
//  S = (2*sx*sy + C1')(2*cn*(49*sxy - sx*sy) + C2')
//      / ((sx^2+sy^2 + C1')(cn*(49*(sxx+syy) - sx^2 - sy^2) + C2'))
// with C1' = 2401*(0.01*R)^2, C2' = 2401*(0.03*R)^2.
__global__ __launch_bounds__(TW) void ssim_kernel(
    const float* __restrict__ pred, const float* __restrict__ gt)
{
    __shared__ float s_x[TW + 8];
    __shared__ float s_y[TW + 8];
    __shared__ float s_ring[7][5][TW];   // vertical sliding-window history
    __shared__ float s_red[8];

    const int t  = threadIdx.x;
    const int c0 = blockIdx.x * TW;
    const int r0 = blockIdx.y * RH;
    const int chunk = min(RH, OUTH - r0);
    const int nrows = chunk + 6;

    const float rng = g_max - g_min;
    float c1 = 0.01f * rng; c1 = 2401.f * c1 * c1;
    float c2 = 0.03f * rng; c2 = 2401.f * c2 * c2;
    const float CN  = 49.f / 48.f;
    const float CN2 = 2.f * CN;

    // zero ring (thread-private columns)
    #pragma unroll
    for (int s = 0; s < 7; s++)
        #pragma unroll
        for (int q = 0; q < 5; q++)
            s_ring[s][q][t] = 0.f;

    float v0 = 0.f, v1 = 0.f, v2 = 0.f, v3 = 0.f, v4 = 0.f;
    float acc = 0.f;
    const bool colv = (c0 + t) < OUTW;

    int slot = 0;
    for (int ir = 0; ir < nrows; ir++) {
        const size_t base = (size_t)(r0 + ir) * W + c0;
        __syncthreads();                    // previous row fully consumed
        for (int i = t; i < TW + 6; i += TW) {
            bool ok = (c0 + i) < W;
            s_x[i] = ok ? gt[base + i]   : 0.f;
            s_y[i] = ok ? pred[base + i] : 0.f;
        }
        __syncthreads();

        // horizontal 7-tap sums of {x, y, xx, yy, xy}
        float hx = 0.f, hy = 0.f, hxx = 0.f, hyy = 0.f, hxy = 0.f;
        #pragma unroll
        for (int k = 0; k < 7; k++) {
            float a = s_x[t + k];
            float b = s_y[t + k];
            hx += a;  hy += b;
            hxx = fmaf(a, a, hxx);
            hyy = fmaf(b, b, hyy);
            hxy = fmaf(a, b, hxy);
        }

        // vertical sliding window via 7-deep ring
        v0 += hx  - s_ring[slot][0][t]; s_ring[slot][0][t] = hx;
        v1 += hy  - s_ring[slot][1][t]; s_ring[slot][1][t] = hy;
        v2 += hxx - s_ring[slot][2][t]; s_ring[slot][2][t] = hxx;
        v3 += hyy - s_ring[slot][3][t]; s_ring[slot][3][t] = hyy;
        v4 += hxy - s_ring[slot][4][t]; s_ring[slot][4][t] = hxy;
        slot = (slot == 6) ? 0 : slot + 1;

        if (ir >= 6 && colv) {
            float AB   = v0 * v1;
            float A2B2 = fmaf(v0, v0, v1 * v1);
            float num1 = fmaf(2.f, AB, c1);
            float den1 = A2B2 + c1;
            float num2 = fmaf(CN2, fmaf(49.f, v4, -AB), c2);
            float den2 = fmaf(CN,  fmaf(49.f, v2 + v3, -A2B2), c2);
            acc += __fdividef(num1 * num2, den1 * den2);
        }
    }

    // block reduction of SSIM partial
    #pragma unroll
    for (int o = 16; o > 0; o >>= 1)
        acc += __shfl_down_sync(0xffffffffu, acc, o);
    if ((t & 31) == 0) s_red[t >> 5] = acc;
    __syncthreads();
    if (t < 8) {
        float a = s_red[t];
        #pragma unroll
        for (int o = 4; o > 0; o >>= 1)
            a += __shfl_down_sync(0xffu, a, o);
        if (t == 0) atomicAdd(&g_ssim_sum, (double)a);
    }
}

// ---------------- finalize ----------------
__global__ void finalize_kernel(float* out) {
    double mse   = g_mse_sum  / ((double)W * (double)H);
    double mssim = g_ssim_sum / ((double)OUTW * (double)OUTH);
    out[0] = (float)(mse * exp(1.0 - mssim));
}

// ---------------- launcher ----------------
extern "C" void kernel_launch(void* const* d_in, const int* in_sizes, int n_in,
                              void* d_out, int out_size)
{
    const float* pred = (const float*)d_in[0];   // depth_pred
    const float* gt   = (const float*)d_in[1];   // depth_gt

    init_kernel<<<1, 1>>>();

    int n4 = (W * H) / 4;
    reduce_kernel<<<2368, 256>>>((const float4*)pred, (const float4*)gt, n4);

    dim3 grid((OUTW + TW - 1) / TW, (OUTH + RH - 1) / RH);
    ssim_kernel<<<grid, TW>>>(pred, gt);

    finalize_kernel<<<1, 1>>>((float*)d_out);
}

// round 3
// speedup vs baseline: 1.4699x; 1.4699x over previous
#include <cuda_runtime.h>
#include <math.h>
#include <stdint.h>

// Problem constants (4096 x 4096 fp32 images, 7x7 SSIM window)
#define W     4096
#define H     4096
#define OUTW  4090      // W - 6 (VALID 7x7)
#define OUTH  4090

#define TPB    64       // threads per ssim block
#define CPT    4        // output columns per thread
#define TWOUT  (TPB*CPT)       // 256 output cols per block
#define NCHUNK (TPB + 2)       // float4 chunks staged (covers TWOUT+8 floats)
#define RH     75              // output rows per block strip
#define GY     55              // ceil(4090/75)

// ---------------- device scratch (no allocations allowed) ----------------
__device__ double g_mse_sum;
__device__ double g_ssim_sum;
__device__ float  g_min;
__device__ float  g_max;

__global__ void init_kernel() {
    g_mse_sum  = 0.0;
    g_ssim_sum = 0.0;
    g_min = __int_as_float(0x7f800000);   // +inf
    g_max = __int_as_float(0xff800000);   // -inf
}

__device__ __forceinline__ void atomicMaxF(float* a, float v) {
    if (v >= 0.f) atomicMax((int*)a, __float_as_int(v));
    else          atomicMin((unsigned int*)a, __float_as_uint(v));
}
__device__ __forceinline__ void atomicMinF(float* a, float v) {
    if (v >= 0.f) atomicMin((int*)a, __float_as_int(v));
    else          atomicMax((unsigned int*)a, __float_as_uint(v));
}

// ---------------- pass 1: mse sum + min/max of pred ----------------
__global__ __launch_bounds__(256) void reduce_kernel(
    const float4* __restrict__ pred, const float4* __restrict__ gt, int n4)
{
    float mse = 0.f;
    float mn  = __int_as_float(0x7f800000);
    float mx  = __int_as_float(0xff800000);

    for (int i = blockIdx.x * blockDim.x + threadIdx.x; i < n4;
         i += gridDim.x * blockDim.x) {
        float4 p = pred[i];
        float4 g = gt[i];
        float d0 = p.x - g.x, d1 = p.y - g.y, d2 = p.z - g.z, d3 = p.w - g.w;
        mse = fmaf(d0, d0, mse);
        mse = fmaf(d1, d1, mse);
        mse = fmaf(d2, d2, mse);
        mse = fmaf(d3, d3, mse);
        mn = fminf(mn, fminf(fminf(p.x, p.y), fminf(p.z, p.w)));
        mx = fmaxf(mx, fmaxf(fmaxf(p.x, p.y), fmaxf(p.z, p.w)));
    }
    #pragma unroll
    for (int o = 16; o > 0; o >>= 1) {
        mse += __shfl_down_sync(0xffffffffu, mse, o);
        mn = fminf(mn, __shfl_down_sync(0xffffffffu, mn, o));
        mx = fmaxf(mx, __shfl_down_sync(0xffffffffu, mx, o));
    }
    __shared__ float smse[8], smn[8], smx[8];
    int lane = threadIdx.x & 31, wid = threadIdx.x >> 5;
    if (lane == 0) { smse[wid] = mse; smn[wid] = mn; smx[wid] = mx; }
    __syncthreads();
    if (threadIdx.x < 8) {
        float a = smse[threadIdx.x];
        float b = smn[threadIdx.x];
        float c = smx[threadIdx.x];
        #pragma unroll
        for (int o = 4; o > 0; o >>= 1) {
            a += __shfl_down_sync(0xffu, a, o);
            b = fminf(b, __shfl_down_sync(0xffu, b, o));
            c = fmaxf(c, __shfl_down_sync(0xffu, c, o));
        }
        if (threadIdx.x == 0) {
            atomicAdd(&g_mse_sum, (double)a);
            atomicMinF(&g_min, b);
            atomicMaxF(&g_max, c);
        }
    }
}

// ---------------- pass 2: SSIM map sum ----------------
// Sum/difference decomposition: s = x+y, d = x-y. Window sums
//   A = sum(s), B = sum(d), P = sum(s^2), Q = sum(d^2)
// give (rescaled so num/den scale factors cancel):
//   num1 = A^2-B^2 + C1a        den1 = A^2+B^2 + C1a
//   num2 = TC*(49(P-Q)-(A^2-B^2)) + C2a
//   den2 = TC*(49(P+Q)-(A^2+B^2)) + C2a
// with TC = 2*49/48, C1a = 2*2401*(K1*R)^2, C2a = 4*2401*(K2*R)^2.
// S = num1*num2 / (den1*den2).

// horizontal 7-tap sums for 4 adjacent output cols; own chunk e in regs,
// neighbor chunks from smem.
__device__ __forceinline__ float4 hsum7(float4 e, const float4* __restrict__ arr, int t)
{
    float4 n = arr[t + 1];
    float2 m = *(const float2*)(arr + t + 2);
    float4 h;
    h.x = e.x + e.y + e.z + e.w + n.x + n.y + n.z;
    h.y = h.x - e.x + n.w;
    h.z = h.y - e.y + m.x;
    h.w = h.z - e.z + m.y;
    return h;
}

__global__ __launch_bounds__(TPB) void ssim_kernel(
    const float* __restrict__ pred, const float* __restrict__ gt)
{
    __shared__ float4 s_st[4][NCHUNK];        // staged s, d, s^2, d^2 (one row)
    __shared__ float4 s_ring[4][7][TPB];      // vertical 7-row ring (thread-private cols)
    __shared__ float  s_red[2];

    const int t  = threadIdx.x;
    const int c0 = blockIdx.x * TWOUT;
    const int r0 = blockIdx.y * RH;
    const int chunk_rows = min(RH, OUTH - r0);
    const int nrows = chunk_rows + 6;

    const float rng = g_max - g_min;
    float k1 = 0.01f * rng, k2 = 0.03f * rng;
    const float C1a = 2.f * 2401.f * k1 * k1;
    const float C2a = 4.f * 2401.f * k2 * k2;
    const float TC  = 49.f / 24.f;            // 2 * 49/48

    // zero the ring (thread-private slots, no barrier needed)
    const float4 z4 = make_float4(0.f, 0.f, 0.f, 0.f);
    #pragma unroll
    for (int sct = 0; sct < 7; sct++) {
        s_ring[0][sct][t] = z4; s_ring[1][sct][t] = z4;
        s_ring[2][sct][t] = z4; s_ring[3][sct][t] = z4;
    }

    float4 vA = z4, vB = z4, vP = z4, vQ = z4;   // vertical running sums
    float  acc = 0.f;
    const int colbase = c0 + 4 * t;

    int slot = 0;
    for (int ir = 0; ir < nrows; ir++) {
        const size_t rowoff = (size_t)(r0 + ir) * W;
        const float4* gx = (const float4*)(gt   + rowoff);   // indexed in float4 units
        const float4* gy = (const float4*)(pred + rowoff);
        const int cbase4 = c0 >> 2;                          // chunk index base

        __syncthreads();   // previous row's stage reads are done

        // ---- stage this row: per-element s, d, s^2, d^2 ----
        float4 eA, eB, eP, eQ;   // own chunk kept in registers
        {
            int ck = cbase4 + t;
            float4 xv = (4 * ck < W) ? gx[ck] : z4;
            float4 yv = (4 * ck < W) ? gy[ck] : z4;
            eA.x = xv.x + yv.x; eA.y = xv.y + yv.y; eA.z = xv.z + yv.z; eA.w = xv.w + yv.w;
            eB.x = xv.x - yv.x; eB.y = xv.y - yv.y; eB.z = xv.z - yv.z; eB.w = xv.w - yv.w;
            eP.x = eA.x * eA.x; eP.y = eA.y * eA.y; eP.z = eA.z * eA.z; eP.w = eA.w * eA.w;
            eQ.x = eB.x * eB.x; eQ.y = eB.y * eB.y; eQ.z = eB.z * eB.z; eQ.w = eB.w * eB.w;
            s_st[0][t] = eA; s_st[1][t] = eB; s_st[2][t] = eP; s_st[3][t] = eQ;
        }
        if (t < 2) {   // halo chunks
            int ck = cbase4 + TPB + t;
            float4 xv = (4 * ck < W) ? gx[ck] : z4;
            float4 yv = (4 * ck < W) ? gy[ck] : z4;
            float4 hA, hB, hP, hQ;
            hA.x = xv.x + yv.x; hA.y = xv.y + yv.y; hA.z = xv.z + yv.z; hA.w = xv.w + yv.w;
            hB.x = xv.x - yv.x; hB.y = xv.y - yv.y; hB.z = xv.z - yv.z; hB.w = xv.w - yv.w;
            hP.x = hA.x * hA.x; hP.y = hA.y * hA.y; hP.z = hA.z * hA.z; hP.w = hA.w * hA.w;
            hQ.x = hB.x * hB.x; hQ.y = hB.y * hB.y; hQ.z = hB.z * hB.z; hQ.w = hB.w * hB.w;
            s_st[0][TPB + t] = hA; s_st[1][TPB + t] = hB;
            s_st[2][TPB + t] = hP; s_st[3][TPB + t] = hQ;
        }
        __syncthreads();

        // ---- horizontal 7-tap sums (4 cols per thread) ----
        float4 hA = hsum7(eA, s_st[0], t);
        float4 hB = hsum7(eB, s_st[1], t);
        float4 hP = hsum7(eP, s_st[2], t);
        float4 hQ = hsum7(eQ, s_st[3], t);

        // ---- vertical sliding window via ring ----
        float4 o;
        o = s_ring[0][slot][t];
        vA.x += hA.x - o.x; vA.y += hA.y - o.y; vA.z += hA.z - o.z; vA.w += hA.w - o.w;
        s_ring[0][slot][t] = hA;
        o = s_ring[1][slot][t];
        vB.x += hB.x - o.x; vB.y += hB.y - o.y; vB.z += hB.z - o.z; vB.w += hB.w - o.w;
        s_ring[1][slot][t] = hB;
        o = s_ring[2][slot][t];
        vP.x += hP.x - o.x; vP.y += hP.y - o.y; vP.z += hP.z - o.z; vP.w += hP.w - o.w;
        s_ring[2][slot][t] = hP;
        o = s_ring[3][slot][t];
        vQ.x += hQ.x - o.x; vQ.y += hQ.y - o.y; vQ.z += hQ.z - o.z; vQ.w += hQ.w - o.w;
        s_ring[3][slot][t] = hQ;
        slot = (slot == 6) ? 0 : slot + 1;

        // ---- SSIM evaluation for 4 columns ----
        if (ir >= 6) {
            #pragma unroll
            for (int j = 0; j < 4; j++) {
                float A = (j == 0) ? vA.x : (j == 1) ? vA.y : (j == 2) ? vA.z : vA.w;
                float B = (j == 0) ? vB.x : (j == 1) ? vB.y : (j == 2) ? vB.z : vB.w;
                float P = (j == 0) ? vP.x : (j == 1) ? vP.y : (j == 2) ? vP.z : vP.w;
                float Q = (j == 0) ? vQ.x : (j == 1) ? vQ.y : (j == 2) ? vQ.z : vQ.w;
                float A2 = A * A, B2 = B * B;
                float U = A2 - B2, V = A2 + B2;
                float num1 = U + C1a, den1 = V + C1a;
                float pm = P - Q,  pp = P + Q;
                float num2 = fmaf(TC, fmaf(49.f, pm, -U), C2a);
                float den2 = fmaf(TC, fmaf(49.f, pp, -V), C2a);
                float r = __fdividef(num1 * num2, den1 * den2);
                if (colbase + j < OUTW) acc += r;
            }
        }
    }

    // block reduction (2 warps)
    #pragma unroll
    for (int o = 16; o > 0; o >>= 1)
        acc += __shfl_down_sync(0xffffffffu, acc, o);
    if ((t & 31) == 0) s_red[t >> 5] = acc;
    __syncthreads();
    if (t == 0)
        atomicAdd(&g_ssim_sum, (double)(s_red[0] + s_red[1]));
}

// ---------------- finalize ----------------
__global__ void finalize_kernel(float* out) {
    double mse   = g_mse_sum  / ((double)W * (double)H);
    double mssim = g_ssim_sum / ((double)OUTW * (double)OUTH);
    out[0] = (float)(mse * exp(1.0 - mssim));
}

// ---------------- launcher ----------------
extern "C" void kernel_launch(void* const* d_in, const int* in_sizes, int n_in,
                              void* d_out, int out_size)
{
    const float* pred = (const float*)d_in[0];   // depth_pred
    const float* gt   = (const float*)d_in[1];   // depth_gt

    init_kernel<<<1, 1>>>();

    int n4 = (W * H) / 4;
    reduce_kernel<<<2368, 256>>>((const float4*)pred, (const float4*)gt, n4);

    dim3 grid((OUTW + TWOUT - 1) / TWOUT, GY);   // (16, 55)
    ssim_kernel<<<grid, TPB>>>(pred, gt);

    finalize_kernel<<<1, 1>>>((float*)d_out);
}

// round 4
// speedup vs baseline: 2.2780x; 1.5498x over previous
#include <cuda_runtime.h>
#include <math.h>
#include <stdint.h>

// Problem constants (4096 x 4096 fp32 images, 7x7 SSIM window)
#define W     4096
#define H     4096
#define OUTW  4090      // W - 6 (VALID 7x7)
#define OUTH  4090

#define STRIPW 128      // output columns per warp (32 lanes x 4 cols)
#define NSTRIP 32       // ceil(4090/128)
#define RH     82       // output rows per block strip
#define GY     50       // ceil(4090/82)

// ---------------- device scratch (no allocations allowed) ----------------
__device__ double g_mse_sum;
__device__ double g_ssim_sum;
__device__ float  g_min;
__device__ float  g_max;

__global__ void init_kernel() {
    g_mse_sum  = 0.0;
    g_ssim_sum = 0.0;
    g_min = __int_as_float(0x7f800000);   // +inf
    g_max = __int_as_float(0xff800000);   // -inf
}

__device__ __forceinline__ void atomicMaxF(float* a, float v) {
    if (v >= 0.f) atomicMax((int*)a, __float_as_int(v));
    else          atomicMin((unsigned int*)a, __float_as_uint(v));
}
__device__ __forceinline__ void atomicMinF(float* a, float v) {
    if (v >= 0.f) atomicMin((int*)a, __float_as_int(v));
    else          atomicMax((unsigned int*)a, __float_as_uint(v));
}

// ---------------- pass 1: mse sum + min/max of pred ----------------
__global__ __launch_bounds__(256) void reduce_kernel(
    const float4* __restrict__ pred, const float4* __restrict__ gt, int n4)
{
    float mse = 0.f;
    float mn  = __int_as_float(0x7f800000);
    float mx  = __int_as_float(0xff800000);

    for (int i = blockIdx.x * blockDim.x + threadIdx.x; i < n4;
         i += gridDim.x * blockDim.x) {
        float4 p = pred[i];
        float4 g = gt[i];
        float d0 = p.x - g.x, d1 = p.y - g.y, d2 = p.z - g.z, d3 = p.w - g.w;
        mse = fmaf(d0, d0, mse);
        mse = fmaf(d1, d1, mse);
        mse = fmaf(d2, d2, mse);
        mse = fmaf(d3, d3, mse);
        mn = fminf(mn, fminf(fminf(p.x, p.y), fminf(p.z, p.w)));
        mx = fmaxf(mx, fmaxf(fmaxf(p.x, p.y), fmaxf(p.z, p.w)));
    }
    #pragma unroll
    for (int o = 16; o > 0; o >>= 1) {
        mse += __shfl_down_sync(0xffffffffu, mse, o);
        mn = fminf(mn, __shfl_down_sync(0xffffffffu, mn, o));
        mx = fmaxf(mx, __shfl_down_sync(0xffffffffu, mx, o));
    }
    __shared__ float smse[8], smn[8], smx[8];
    int lane = threadIdx.x & 31, wid = threadIdx.x >> 5;
    if (lane == 0) { smse[wid] = mse; smn[wid] = mn; smx[wid] = mx; }
    __syncthreads();
    if (threadIdx.x < 8) {
        float a = smse[threadIdx.x];
        float b = smn[threadIdx.x];
        float c = smx[threadIdx.x];
        #pragma unroll
        for (int o = 4; o > 0; o >>= 1) {
            a += __shfl_down_sync(0xffu, a, o);
            b = fminf(b, __shfl_down_sync(0xffu, b, o));
            c = fmaxf(c, __shfl_down_sync(0xffu, c, o));
        }
        if (threadIdx.x == 0) {
            atomicAdd(&g_mse_sum, (double)a);
            atomicMinF(&g_min, b);
            atomicMaxF(&g_max, c);
        }
    }
}

// ---------------- pass 2: SSIM map sum ----------------
// Sum/difference decomposition: s = x+y, d = x-y. Window sums
//   A = sum(s), B = sum(d), P = sum(s^2), Q = sum(d^2)
// give (rescaled so num/den scale factors cancel):
//   num1 = A^2-B^2 + C1a        den1 = A^2+B^2 + C1a
//   num2 = TC*(49(P-Q)-(A^2-B^2)) + C2a
//   den2 = TC*(49(P+Q)-(A^2+B^2)) + C2a
// with TC = 2*49/48, C1a = 2*2401*(K1*R)^2, C2a = 4*2401*(K2*R)^2.
// S = num1*num2 / (den1*den2).
//
// One warp per block, no __syncthreads anywhere in the main loop. Each lane
// owns 4 output columns and loads its 10 input elements directly (own float4
// + overlapping float4 + float2); redundancy is absorbed by L1/L2. Next row's
// loads are issued before current row's compute (software pipeline).

__device__ __forceinline__ float4 h7(const float* e)   // 7-tap sums, 4 windows
{
    float4 h;
    h.x = e[0] + e[1] + e[2] + e[3] + e[4] + e[5] + e[6];
    h.y = h.x - e[0] + e[7];
    h.z = h.y - e[1] + e[8];
    h.w = h.z - e[2] + e[9];
    return h;
}

__global__ __launch_bounds__(32) void ssim_kernel(
    const float* __restrict__ pred, const float* __restrict__ gt)
{
    __shared__ float4 s_ring[4][7][32];   // vertical 7-row ring, lane-private

    const int l  = threadIdx.x;
    const int c0 = blockIdx.x * STRIPW;
    const int r0 = blockIdx.y * RH;
    const int chunk_rows = min(RH, OUTH - r0);
    const int nrows = chunk_rows + 6;

    const float rng = g_max - g_min;
    float k1 = 0.01f * rng, k2 = 0.03f * rng;
    const float C1a = 2.f * 2401.f * k1 * k1;
    const float C2a = 4.f * 2401.f * k2 * k2;
    const float TC  = 49.f / 24.f;            // 2 * 49/48

    const int cb = c0 + 4 * l;                // first input col of this lane
    const bool ok1 = (cb + 7) < W;            // float4 at cb+4 in range
    const bool ok2 = (cb + 9) < W;            // float2 at cb+8 in range

    const float4 z4 = make_float4(0.f, 0.f, 0.f, 0.f);
    const float2 z2 = make_float2(0.f, 0.f);

    #pragma unroll
    for (int sct = 0; sct < 7; sct++) {
        s_ring[0][sct][l] = z4; s_ring[1][sct][l] = z4;
        s_ring[2][sct][l] = z4; s_ring[3][sct][l] = z4;
    }

    float4 vA = z4, vB = z4, vP = z4, vQ = z4;
    float  acc = 0.f;

    // prime the pipeline: load row r0
    const float* gx0 = gt   + (size_t)r0 * W;
    const float* gy0 = pred + (size_t)r0 * W;
    float4 cx0 = *(const float4*)(gx0 + cb);
    float4 cx1 = ok1 ? *(const float4*)(gx0 + cb + 4) : z4;
    float2 cx2 = ok2 ? *(const float2*)(gx0 + cb + 8) : z2;
    float4 cy0 = *(const float4*)(gy0 + cb);
    float4 cy1 = ok1 ? *(const float4*)(gy0 + cb + 4) : z4;
    float2 cy2 = ok2 ? *(const float2*)(gy0 + cb + 8) : z2;

    int slot = 0;
    for (int ir = 0; ir < nrows; ir++) {
        // ---- prefetch next row (clamped; last iter's values unused) ----
        int rn = r0 + min(ir + 1, nrows - 1);
        const float* gxn = gt   + (size_t)rn * W;
        const float* gyn = pred + (size_t)rn * W;
        float4 nx0 = *(const float4*)(gxn + cb);
        float4 nx1 = ok1 ? *(const float4*)(gxn + cb + 4) : z4;
        float2 nx2 = ok2 ? *(const float2*)(gxn + cb + 8) : z2;
        float4 ny0 = *(const float4*)(gyn + cb);
        float4 ny1 = ok1 ? *(const float4*)(gyn + cb + 4) : z4;
        float2 ny2 = ok2 ? *(const float2*)(gyn + cb + 8) : z2;

        // ---- per-element s, d, s^2, d^2 for the 10 columns ----
        float xs[10] = {cx0.x, cx0.y, cx0.z, cx0.w,
                        cx1.x, cx1.y, cx1.z, cx1.w, cx2.x, cx2.y};
        float ys[10] = {cy0.x, cy0.y, cy0.z, cy0.w,
                        cy1.x, cy1.y, cy1.z, cy1.w, cy2.x, cy2.y};
        float eA[10], eB[10], eP[10], eQ[10];
        #pragma unroll
        for (int i = 0; i < 10; i++) {
            float s = xs[i] + ys[i];
            float d = xs[i] - ys[i];
            eA[i] = s; eB[i] = d;
            eP[i] = s * s; eQ[i] = d * d;
        }

        // ---- horizontal 7-tap sums (4 windows per lane) ----
        float4 hA = h7(eA);
        float4 hB = h7(eB);
        float4 hP = h7(eP);
        float4 hQ = h7(eQ);

        // ---- vertical sliding window via lane-private ring ----
        float4 o;
        o = s_ring[0][slot][l];
        vA.x += hA.x - o.x; vA.y += hA.y - o.y; vA.z += hA.z - o.z; vA.w += hA.w - o.w;
        s_ring[0][slot][l] = hA;
        o = s_ring[1][slot][l];
        vB.x += hB.x - o.x; vB.y += hB.y - o.y; vB.z += hB.z - o.z; vB.w += hB.w - o.w;
        s_ring[1][slot][l] = hB;
        o = s_ring[2][slot][l];
        vP.x += hP.x - o.x; vP.y += hP.y - o.y; vP.z += hP.z - o.z; vP.w += hP.w - o.w;
        s_ring[2][slot][l] = hP;
        o = s_ring[3][slot][l];
        vQ.x += hQ.x - o.x; vQ.y += hQ.y - o.y; vQ.z += hQ.z - o.z; vQ.w += hQ.w - o.w;
        s_ring[3][slot][l] = hQ;
        slot = (slot == 6) ? 0 : slot + 1;

        // ---- SSIM evaluation for 4 columns ----
        if (ir >= 6) {
            #pragma unroll
            for (int j = 0; j < 4; j++) {
                float A = (j == 0) ? vA.x : (j == 1) ? vA.y : (j == 2) ? vA.z : vA.w;
                float B = (j == 0) ? vB.x : (j == 1) ? vB.y : (j == 2) ? vB.z : vB.w;
                float P = (j == 0) ? vP.x : (j == 1) ? vP.y : (j == 2) ? vP.z : vP.w;
                float Q = (j == 0) ? vQ.x : (j == 1) ? vQ.y : (j == 2) ? vQ.z : vQ.w;
                float A2 = A * A, B2 = B * B;
                float U = A2 - B2, V = A2 + B2;
                float num1 = U + C1a, den1 = V + C1a;
                float pm = P - Q,  pp = P + Q;
                float num2 = fmaf(TC, fmaf(49.f, pm, -U), C2a);
                float den2 = fmaf(TC, fmaf(49.f, pp, -V), C2a);
                float r = __fdividef(num1 * num2, den1 * den2);
                if (cb + j < OUTW) acc += r;
            }
        }

        // rotate pipeline registers
        cx0 = nx0; cx1 = nx1; cx2 = nx2;
        cy0 = ny0; cy1 = ny1; cy2 = ny2;
    }

    // warp reduction + one atomic per warp
    #pragma unroll
    for (int o = 16; o > 0; o >>= 1)
        acc += __shfl_down_sync(0xffffffffu, acc, o);
    if (l == 0)
        atomicAdd(&g_ssim_sum, (double)acc);
}

// ---------------- finalize ----------------
__global__ void finalize_kernel(float* out) {
    double mse   = g_mse_sum  / ((double)W * (double)H);
    double mssim = g_ssim_sum / ((double)OUTW * (double)OUTH);
    out[0] = (float)(mse * exp(1.0 - mssim));
}

// ---------------- launcher ----------------
extern "C" void kernel_launch(void* const* d_in, const int* in_sizes, int n_in,
                              void* d_out, int out_size)
{
    const float* pred = (const float*)d_in[0];   // depth_pred
    const float* gt   = (const float*)d_in[1];   // depth_gt

    init_kernel<<<1, 1>>>();

    int n4 = (W * H) / 4;
    reduce_kernel<<<2368, 256>>>((const float4*)pred, (const float4*)gt, n4);

    dim3 grid(NSTRIP, GY);   // (32, 50), one warp per block
    ssim_kernel<<<grid, 32>>>(pred, gt);

    finalize_kernel<<<1, 1>>>((float*)d_out);
}

// round 5
// speedup vs baseline: 2.6056x; 1.1438x over previous
#include <cuda_runtime.h>
#include <math.h>
#include <stdint.h>

typedef unsigned long long ull;

// Problem constants (4096 x 4096 fp32 images, 7x7 SSIM window)
#define W     4096
#define H     4096
#define OUTW  4090      // W - 6 (VALID 7x7)
#define OUTH  4090

#define STRIPW 128      // output columns per warp (32 lanes x 4 cols)
#define NSTRIP 32       // ceil(4090/128)
#define RH     82       // output rows per block strip
#define GY     50       // ceil(4090/82)
#define NBLK   (NSTRIP * GY)   // 1600 ssim blocks

// ---------------- device scratch (statically initialized; the last ssim
// block resets everything so each graph replay starts clean) ---------------
__device__ double g_mse_sum  = 0.0;
__device__ double g_ssim_sum = 0.0;
__device__ float  g_min =  1e30f;
__device__ float  g_max = -1e30f;
__device__ unsigned int g_done = 0;

__device__ __forceinline__ void atomicMaxF(float* a, float v) {
    if (v >= 0.f) atomicMax((int*)a, __float_as_int(v));
    else          atomicMin((unsigned int*)a, __float_as_uint(v));
}
__device__ __forceinline__ void atomicMinF(float* a, float v) {
    if (v >= 0.f) atomicMin((int*)a, __float_as_int(v));
    else          atomicMax((unsigned int*)a, __float_as_uint(v));
}

// ---------------- packed f32x2 helpers (sm_100a) ----------------
__device__ __forceinline__ ull F2ADD(ull a, ull b) {
    ull r; asm("add.rn.f32x2 %0,%1,%2;" : "=l"(r) : "l"(a), "l"(b)); return r;
}
__device__ __forceinline__ ull F2MUL(ull a, ull b) {
    ull r; asm("mul.rn.f32x2 %0,%1,%2;" : "=l"(r) : "l"(a), "l"(b)); return r;
}
__device__ __forceinline__ ull F2FMA(ull a, ull b, ull c) {
    ull r; asm("fma.rn.f32x2 %0,%1,%2,%3;" : "=l"(r) : "l"(a), "l"(b), "l"(c)); return r;
}
__device__ __forceinline__ ull F2PACK(float lo, float hi) {
    ull r; asm("mov.b64 %0,{%1,%2};" : "=l"(r) : "f"(lo), "f"(hi)); return r;
}
__device__ __forceinline__ void F2UNPACK(ull a, float& lo, float& hi) {
    asm("mov.b64 {%0,%1},%2;" : "=f"(lo), "=f"(hi) : "l"(a));
}

// ---------------- pass 1: min/max of pred + MSE of rows 0..5 ----------------
// (MSE of rows >= 6 is accumulated inside the ssim kernel, which tiles those
//  rows exactly once across strips.)
#define MSE_ROWS4 ((6 * W) / 4)   // first 6 rows in float4 units

__global__ __launch_bounds__(256) void reduce_kernel(
    const float4* __restrict__ pred, const float4* __restrict__ gt, int n4)
{
    float mse = 0.f;
    float mn  = 1e30f;
    float mx  = -1e30f;

    for (int i = blockIdx.x * blockDim.x + threadIdx.x; i < n4;
         i += gridDim.x * blockDim.x) {
        float4 p = pred[i];
        mn = fminf(mn, fminf(fminf(p.x, p.y), fminf(p.z, p.w)));
        mx = fmaxf(mx, fmaxf(fmaxf(p.x, p.y), fmaxf(p.z, p.w)));
        if (i < MSE_ROWS4) {
            float4 g = gt[i];
            float d0 = p.x - g.x, d1 = p.y - g.y, d2 = p.z - g.z, d3 = p.w - g.w;
            mse = fmaf(d0, d0, mse);
            mse = fmaf(d1, d1, mse);
            mse = fmaf(d2, d2, mse);
            mse = fmaf(d3, d3, mse);
        }
    }
    #pragma unroll
    for (int o = 16; o > 0; o >>= 1) {
        mse += __shfl_down_sync(0xffffffffu, mse, o);
        mn = fminf(mn, __shfl_down_sync(0xffffffffu, mn, o));
        mx = fmaxf(mx, __shfl_down_sync(0xffffffffu, mx, o));
    }
    __shared__ float smse[8], smn[8], smx[8];
    int lane = threadIdx.x & 31, wid = threadIdx.x >> 5;
    if (lane == 0) { smse[wid] = mse; smn[wid] = mn; smx[wid] = mx; }
    __syncthreads();
    if (threadIdx.x < 8) {
        float a = smse[threadIdx.x];
        float b = smn[threadIdx.x];
        float c = smx[threadIdx.x];
        #pragma unroll
        for (int o = 4; o > 0; o >>= 1) {
            a += __shfl_down_sync(0xffu, a, o);
            b = fminf(b, __shfl_down_sync(0xffu, b, o));
            c = fmaxf(c, __shfl_down_sync(0xffu, c, o));
        }
        if (threadIdx.x == 0) {
            if (a != 0.f) atomicAdd(&g_mse_sum, (double)a);
            atomicMinF(&g_min, b);
            atomicMaxF(&g_max, c);
        }
    }
}

// ---------------- pass 2: SSIM map sum + MSE tail + fused finalize --------
// Sum/difference decomposition: s = x+y, d = x-y. Window sums
//   A = sum(s), B = sum(d), P = sum(s^2), Q = sum(d^2)
// give (rescaled so num/den scale factors cancel):
//   num1 = A^2-B^2 + C1a        den1 = A^2+B^2 + C1a
//   num2 = TC*(49(P-Q)-(A^2-B^2)) + C2a
//   den2 = TC*(49(P+Q)-(A^2+B^2)) + C2a
// with TC = 2*49/48, C1a = 2*2401*(K1*R)^2, C2a = 4*2401*(K2*R)^2.
// One warp per block; no barriers; packed f32x2 for element, vertical and
// evaluation stages; scalar horizontal 7-tap (pack-shuffle costs more than
// it saves there).

__global__ __launch_bounds__(32) void ssim_kernel(
    const float* __restrict__ pred, const float* __restrict__ gt, float* __restrict__ out)
{
    __shared__ ulonglong2 s_ring[4][7][32];   // vertical 7-row ring, lane-private

    const int l  = threadIdx.x;
    const int c0 = blockIdx.x * STRIPW;
    const int r0 = blockIdx.y * RH;
    const int chunk_rows = min(RH, OUTH - r0);
    const int nrows = chunk_rows + 6;

    const float rng = g_max - g_min;
    float k1 = 0.01f * rng, k2 = 0.03f * rng;
    const float C1a = 2.f * 2401.f * k1 * k1;
    const float C2a = 4.f * 2401.f * k2 * k2;

    const ull C1a2 = F2PACK(C1a, C1a);
    const ull C2a2 = F2PACK(C2a, C2a);
    const ull K49  = F2PACK(49.f, 49.f);
    const ull TC2  = F2PACK(49.f / 24.f, 49.f / 24.f);
    const ull NEG1 = F2PACK(-1.f, -1.f);
    const ull ZERO = 0ull;

    const int cb = c0 + 4 * l;                // first input col of this lane
    const bool ok1 = (cb + 7) < W;            // 2nd float4 in range
    const bool ok2 = (cb + 9) < W;            // trailing float2 in range

    #pragma unroll
    for (int sct = 0; sct < 7; sct++) {
        ulonglong2 z2; z2.x = 0ull; z2.y = 0ull;
        s_ring[0][sct][l] = z2; s_ring[1][sct][l] = z2;
        s_ring[2][sct][l] = z2; s_ring[3][sct][l] = z2;
    }

    ull vA01 = 0, vA23 = 0, vB01 = 0, vB23 = 0;
    ull vP01 = 0, vP23 = 0, vQ01 = 0, vQ23 = 0;
    ull macc = 0;                              // packed MSE accumulator
    float acc = 0.f;

    // prime the pipeline: load row r0 (pairs directly as ull)
    const float* gx0 = gt   + (size_t)r0 * W;
    const float* gy0 = pred + (size_t)r0 * W;
    ulonglong2 cxa = *(const ulonglong2*)(gx0 + cb);                 // cols 0..3
    ulonglong2 cxb = ok1 ? *(const ulonglong2*)(gx0 + cb + 4)
                         : make_ulonglong2(0ull, 0ull);              // cols 4..7
    ull        cxc = ok2 ? *(const ull*)(gx0 + cb + 8) : 0ull;       // cols 8..9
    ulonglong2 cya = *(const ulonglong2*)(gy0 + cb);
    ulonglong2 cyb = ok1 ? *(const ulonglong2*)(gy0 + cb + 4)
                         : make_ulonglong2(0ull, 0ull);
    ull        cyc = ok2 ? *(const ull*)(gy0 + cb + 8) : 0ull;

    int slot = 0;
    for (int ir = 0; ir < nrows; ir++) {
        // ---- prefetch next row (clamped; final iter's values unused) ----
        int rn = r0 + min(ir + 1, nrows - 1);
        const float* gxn = gt   + (size_t)rn * W;
        const float* gyn = pred + (size_t)rn * W;
        ulonglong2 nxa = *(const ulonglong2*)(gxn + cb);
        ulonglong2 nxb = ok1 ? *(const ulonglong2*)(gxn + cb + 4)
                             : make_ulonglong2(0ull, 0ull);
        ull        nxc = ok2 ? *(const ull*)(gxn + cb + 8) : 0ull;
        ulonglong2 nya = *(const ulonglong2*)(gyn + cb);
        ulonglong2 nyb = ok1 ? *(const ulonglong2*)(gyn + cb + 4)
                             : make_ulonglong2(0ull, 0ull);
        ull        nyc = ok2 ? *(const ull*)(gyn + cb + 8) : 0ull;

        // ---- packed elements: s, d, s^2, d^2 for 5 pairs ----
        ull pA0 = F2ADD(cxa.x, cya.x), pA1 = F2ADD(cxa.y, cya.y);
        ull pA2 = F2ADD(cxb.x, cyb.x), pA3 = F2ADD(cxb.y, cyb.y);
        ull pA4 = F2ADD(cxc,   cyc);
        ull pB0 = F2FMA(cya.x, NEG1, cxa.x), pB1 = F2FMA(cya.y, NEG1, cxa.y);
        ull pB2 = F2FMA(cyb.x, NEG1, cxb.x), pB3 = F2FMA(cyb.y, NEG1, cxb.y);
        ull pB4 = F2FMA(cyc,   NEG1, cxc);
        ull pP0 = F2MUL(pA0, pA0), pP1 = F2MUL(pA1, pA1);
        ull pP2 = F2MUL(pA2, pA2), pP3 = F2MUL(pA3, pA3);
        ull pP4 = F2MUL(pA4, pA4);
        ull pQ0 = F2MUL(pB0, pB0), pQ1 = F2MUL(pB1, pB1);
        ull pQ2 = F2MUL(pB2, pB2), pQ3 = F2MUL(pB3, pB3);
        ull pQ4 = F2MUL(pB4, pB4);

        // ---- scalar horizontal 7-tap sums, then pack ----
        ull hA01, hA23, hB01, hB23, hP01, hP23, hQ01, hQ23;
        {
            float e0, e1, e2, e3, e4, e5, e6, e7, e8, e9, h0, h1, h2, h3;
            F2UNPACK(pA0, e0, e1); F2UNPACK(pA1, e2, e3); F2UNPACK(pA2, e4, e5);
            F2UNPACK(pA3, e6, e7); F2UNPACK(pA4, e8, e9);
            h0 = e0 + e1 + e2 + e3 + e4 + e5 + e6;
            h1 = h0 - e0 + e7; h2 = h1 - e1 + e8; h3 = h2 - e2 + e9;
            hA01 = F2PACK(h0, h1); hA23 = F2PACK(h2, h3);
            F2UNPACK(pB0, e0, e1); F2UNPACK(pB1, e2, e3); F2UNPACK(pB2, e4, e5);
            F2UNPACK(pB3, e6, e7); F2UNPACK(pB4, e8, e9);
            h0 = e0 + e1 + e2 + e3 + e4 + e5 + e6;
            h1 = h0 - e0 + e7; h2 = h1 - e1 + e8; h3 = h2 - e2 + e9;
            hB01 = F2PACK(h0, h1); hB23 = F2PACK(h2, h3);
            F2UNPACK(pP0, e0, e1); F2UNPACK(pP1, e2, e3); F2UNPACK(pP2, e4, e5);
            F2UNPACK(pP3, e6, e7); F2UNPACK(pP4, e8, e9);
            h0 = e0 + e1 + e2 + e3 + e4 + e5 + e6;
            h1 = h0 - e0 + e7; h2 = h1 - e1 + e8; h3 = h2 - e2 + e9;
            hP01 = F2PACK(h0, h1); hP23 = F2PACK(h2, h3);
            F2UNPACK(pQ0, e0, e1); F2UNPACK(pQ1, e2, e3); F2UNPACK(pQ2, e4, e5);
            F2UNPACK(pQ3, e6, e7); F2UNPACK(pQ4, e8, e9);
            h0 = e0 + e1 + e2 + e3 + e4 + e5 + e6;
            h1 = h0 - e0 + e7; h2 = h1 - e1 + e8; h3 = h2 - e2 + e9;
            hQ01 = F2PACK(h0, h1); hQ23 = F2PACK(h2, h3);
        }

        // ---- packed vertical sliding window via lane-private ring ----
        ulonglong2 o2, s2;
        o2 = s_ring[0][slot][l];
        vA01 = F2ADD(vA01, F2FMA(o2.x, NEG1, hA01));
        vA23 = F2ADD(vA23, F2FMA(o2.y, NEG1, hA23));
        s2.x = hA01; s2.y = hA23; s_ring[0][slot][l] = s2;
        o2 = s_ring[1][slot][l];
        vB01 = F2ADD(vB01, F2FMA(o2.x, NEG1, hB01));
        vB23 = F2ADD(vB23, F2FMA(o2.y, NEG1, hB23));
        s2.x = hB01; s2.y = hB23; s_ring[1][slot][l] = s2;
        o2 = s_ring[2][slot][l];
        vP01 = F2ADD(vP01, F2FMA(o2.x, NEG1, hP01));
        vP23 = F2ADD(vP23, F2FMA(o2.y, NEG1, hP23));
        s2.x = hP01; s2.y = hP23; s_ring[2][slot][l] = s2;
        o2 = s_ring[3][slot][l];
        vQ01 = F2ADD(vQ01, F2FMA(o2.x, NEG1, hQ01));
        vQ23 = F2ADD(vQ23, F2FMA(o2.y, NEG1, hQ23));
        s2.x = hQ01; s2.y = hQ23; s_ring[3][slot][l] = s2;
        slot = (slot == 6) ? 0 : slot + 1;

        if (ir >= 6) {
            // ---- MSE over this lane's own 4 columns (tiled exactly once) ----
            macc = F2ADD(macc, pQ0);
            macc = F2ADD(macc, pQ1);

            // ---- packed SSIM evaluation, 2 windows per op ----
            #pragma unroll
            for (int m = 0; m < 2; m++) {
                ull A = m ? vA23 : vA01, B = m ? vB23 : vB01;
                ull P = m ? vP23 : vP01, Q = m ? vQ23 : vQ01;
                ull A2 = F2MUL(A, A);
                ull B2 = F2MUL(B, B);
                ull U  = F2FMA(B2, NEG1, A2);   // A2-B2
                ull V  = F2ADD(A2, B2);
                ull n1 = F2ADD(U, C1a2);
                ull d1 = F2ADD(V, C1a2);
                ull PM = F2FMA(Q, NEG1, P);     // P-Q
                ull PP = F2ADD(P, Q);
                ull nU = F2FMA(A2, NEG1, B2);   // -(A2-B2)
                ull n2 = F2FMA(TC2, F2FMA(K49, PM, nU), C2a2);
                ull nV = F2MUL(V, NEG1);
                ull d2 = F2FMA(TC2, F2FMA(K49, PP, nV), C2a2);
                ull NN = F2MUL(n1, n2);
                ull DD = F2MUL(d1, d2);
                float nn0, nn1, dd0, dd1;
                F2UNPACK(NN, nn0, nn1);
                F2UNPACK(DD, dd0, dd1);
                int j0 = 2 * m;
                if (cb + j0     < OUTW) acc += __fdividef(nn0, dd0);
                if (cb + j0 + 1 < OUTW) acc += __fdividef(nn1, dd1);
            }
        }

        // rotate pipeline registers
        cxa = nxa; cxb = nxb; cxc = nxc;
        cya = nya; cyb = nyb; cyc = nyc;
    }

    // warp reduction + atomics + fused finalize in the last block
    float m0, m1; F2UNPACK(macc, m0, m1);
    float msel = m0 + m1;
    #pragma unroll
    for (int o = 16; o > 0; o >>= 1) {
        acc  += __shfl_down_sync(0xffffffffu, acc, o);
        msel += __shfl_down_sync(0xffffffffu, msel, o);
    }
    if (l == 0) {
        atomicAdd(&g_ssim_sum, (double)acc);
        atomicAdd(&g_mse_sum,  (double)msel);
        __threadfence();
        unsigned int ticket = atomicAdd(&g_done, 1u);
        if (ticket == NBLK - 1) {
            __threadfence();
            double mse   = g_mse_sum  / ((double)W * (double)H);
            double mssim = g_ssim_sum / ((double)OUTW * (double)OUTH);
            out[0] = (float)(mse * exp(1.0 - mssim));
            // reset scratch for the next graph replay
            g_mse_sum  = 0.0;
            g_ssim_sum = 0.0;
            g_min =  1e30f;
            g_max = -1e30f;
            g_done = 0u;
        }
    }
}

// ---------------- launcher ----------------
extern "C" void kernel_launch(void* const* d_in, const int* in_sizes, int n_in,
                              void* d_out, int out_size)
{
    const float* pred = (const float*)d_in[0];   // depth_pred
    const float* gt   = (const float*)d_in[1];   // depth_gt

    int n4 = (W * H) / 4;
    reduce_kernel<<<2368, 256>>>((const float4*)pred, (const float4*)gt, n4);

    dim3 grid(NSTRIP, GY);   // (32, 50), one warp per block
    ssim_kernel<<<grid, 32>>>(pred, gt, (float*)d_out);
}

// round 7
// speedup vs baseline: 2.7558x; 1.0576x over previous
#include <cuda_runtime.h>
#include <math.h>
#include <stdint.h>

typedef unsigned long long ull;

// Problem constants (4096 x 4096 fp32 images, 7x7 SSIM window)
#define W     4096
#define H     4096
#define OUTW  4090      // W - 6 (VALID 7x7)
#define OUTH  4090

#define STRIPW 128      // output columns per warp (32 lanes x 4 cols)
#define NSTRIP 32       // ceil(4090/128)
#define RH     59       // output rows per block strip
#define GY     70       // ceil(4090/59)
#define NBLK   (NSTRIP * GY)   // 2240 ssim blocks (~15.1 per SM, smem-cap fill)

// ---------------- device scratch (statically initialized; the last ssim
// block resets everything so each graph replay starts clean) ---------------
__device__ double g_mse_sum  = 0.0;
__device__ double g_ssim_sum = 0.0;
__device__ float  g_min =  1e30f;
__device__ float  g_max = -1e30f;
__device__ unsigned int g_done = 0;

__device__ __forceinline__ void atomicMaxF(float* a, float v) {
    if (v >= 0.f) atomicMax((int*)a, __float_as_int(v));
    else          atomicMin((unsigned int*)a, __float_as_uint(v));
}
__device__ __forceinline__ void atomicMinF(float* a, float v) {
    if (v >= 0.f) atomicMin((int*)a, __float_as_int(v));
    else          atomicMax((unsigned int*)a, __float_as_uint(v));
}

// ---------------- packed f32x2 helpers (sm_100a) ----------------
__device__ __forceinline__ ull F2ADD(ull a, ull b) {
    ull r; asm("add.rn.f32x2 %0,%1,%2;" : "=l"(r) : "l"(a), "l"(b)); return r;
}
__device__ __forceinline__ ull F2MUL(ull a, ull b) {
    ull r; asm("mul.rn.f32x2 %0,%1,%2;" : "=l"(r) : "l"(a), "l"(b)); return r;
}
__device__ __forceinline__ ull F2FMA(ull a, ull b, ull c) {
    ull r; asm("fma.rn.f32x2 %0,%1,%2,%3;" : "=l"(r) : "l"(a), "l"(b), "l"(c)); return r;
}
__device__ __forceinline__ ull F2PACK(float lo, float hi) {
    ull r; asm("mov.b64 %0,{%1,%2};" : "=l"(r) : "f"(lo), "f"(hi)); return r;
}
__device__ __forceinline__ void F2UNPACK(ull a, float& lo, float& hi) {
    asm("mov.b64 {%0,%1},%2;" : "=f"(lo), "=f"(hi) : "l"(a));
}

// ---------------- pass 1: min/max of pred + MSE of rows 0..5 ----------------
// (MSE of rows >= 6 is accumulated inside the ssim kernel, which tiles those
//  rows exactly once across strips.)
#define MSE_ROWS4 ((6 * W) / 4)   // first 6 rows in float4 units

__global__ __launch_bounds__(256) void reduce_kernel(
    const float4* __restrict__ pred, const float4* __restrict__ gt, int n4)
{
    float mse = 0.f;
    float mn  = 1e30f;
    float mx  = -1e30f;

    for (int i = blockIdx.x * blockDim.x + threadIdx.x; i < n4;
         i += gridDim.x * blockDim.x) {
        float4 p = pred[i];
        mn = fminf(mn, fminf(fminf(p.x, p.y), fminf(p.z, p.w)));
        mx = fmaxf(mx, fmaxf(fmaxf(p.x, p.y), fmaxf(p.z, p.w)));
        if (i < MSE_ROWS4) {
            float4 g = gt[i];
            float d0 = p.x - g.x, d1 = p.y - g.y, d2 = p.z - g.z, d3 = p.w - g.w;
            mse = fmaf(d0, d0, mse);
            mse = fmaf(d1, d1, mse);
            mse = fmaf(d2, d2, mse);
            mse = fmaf(d3, d3, mse);
        }
    }
    #pragma unroll
    for (int o = 16; o > 0; o >>= 1) {
        mse += __shfl_down_sync(0xffffffffu, mse, o);
        mn = fminf(mn, __shfl_down_sync(0xffffffffu, mn, o));
        mx = fmaxf(mx, __shfl_down_sync(0xffffffffu, mx, o));
    }
    __shared__ float smse[8], smn[8], smx[8];
    int lane = threadIdx.x & 31, wid = threadIdx.x >> 5;
    if (lane == 0) { smse[wid] = mse; smn[wid] = mn; smx[wid] = mx; }
    __syncthreads();
    if (threadIdx.x < 8) {
        float a = smse[threadIdx.x];
        float b = smn[threadIdx.x];
        float c = smx[threadIdx.x];
        #pragma unroll
        for (int o = 4; o > 0; o >>= 1) {
            a += __shfl_down_sync(0xffu, a, o);
            b = fminf(b, __shfl_down_sync(0xffu, b, o));
            c = fmaxf(c, __shfl_down_sync(0xffu, c, o));
        }
        if (threadIdx.x == 0) {
            if (a != 0.f) atomicAdd(&g_mse_sum, (double)a);
            atomicMinF(&g_min, b);
            atomicMaxF(&g_max, c);
        }
    }
}

// ---------------- pass 2: SSIM map sum + MSE tail + fused finalize --------
// Sum/difference decomposition: s = x+y, d = x-y. Window sums
//   A = sum(s), B = sum(d), P = sum(s^2), Q = sum(d^2)
// give (rescaled so num/den scale factors cancel):
//   num1 = A^2-B^2 + C1a        den1 = A^2+B^2 + C1a
//   num2 = TC*(49(P-Q)-(A^2-B^2)) + C2a
//   den2 = TC*(49(P+Q)-(A^2+B^2)) + C2a
// with TC = 2*49/48, C1a = 2*2401*(K1*R)^2, C2a = 4*2401*(K2*R)^2.
// One warp per block; no barriers; packed f32x2 for element, vertical and
// evaluation stages; scalar horizontal 7-tap.

__global__ __launch_bounds__(32) void ssim_kernel(
    const float* __restrict__ pred, const float* __restrict__ gt, float* __restrict__ out)
{
    __shared__ ulonglong2 s_ring[4][7][32];   // vertical 7-row ring, lane-private

    const int l  = threadIdx.x;
    const int c0 = blockIdx.x * STRIPW;
    const int r0 = blockIdx.y * RH;
    const int chunk_rows = min(RH, OUTH - r0);
    const int nrows = chunk_rows + 6;

    const float rng = g_max - g_min;
    float k1 = 0.01f * rng, k2 = 0.03f * rng;
    const float C1a = 2.f * 2401.f * k1 * k1;
    const float C2a = 4.f * 2401.f * k2 * k2;

    const ull C1a2 = F2PACK(C1a, C1a);
    const ull C2a2 = F2PACK(C2a, C2a);
    const ull K49  = F2PACK(49.f, 49.f);
    const ull TC2  = F2PACK(49.f / 24.f, 49.f / 24.f);
    const ull NEG1 = F2PACK(-1.f, -1.f);

    const int cb = c0 + 4 * l;                // first input col of this lane
    const bool ok1 = (cb + 7) < W;            // 2nd float4 in range
    const bool ok2 = (cb + 9) < W;            // trailing float2 in range

    #pragma unroll
    for (int sct = 0; sct < 7; sct++) {
        ulonglong2 z2; z2.x = 0ull; z2.y = 0ull;
        s_ring[0][sct][l] = z2; s_ring[1][sct][l] = z2;
        s_ring[2][sct][l] = z2; s_ring[3][sct][l] = z2;
    }

    ull vA01 = 0, vA23 = 0, vB01 = 0, vB23 = 0;
    ull vP01 = 0, vP23 = 0, vQ01 = 0, vQ23 = 0;
    ull macc = 0;                              // packed MSE accumulator
    float acc = 0.f;

    // prime the pipeline: load row r0 (pairs directly as ull)
    const float* gx0 = gt   + (size_t)r0 * W;
    const float* gy0 = pred + (size_t)r0 * W;
    ulonglong2 cxa = *(const ulonglong2*)(gx0 + cb);                 // cols 0..3
    ulonglong2 cxb = ok1 ? *(const ulonglong2*)(gx0 + cb + 4)
                         : make_ulonglong2(0ull, 0ull);              // cols 4..7
    ull        cxc = ok2 ? *(const ull*)(gx0 + cb + 8) : 0ull;       // cols 8..9
    ulonglong2 cya = *(const ulonglong2*)(gy0 + cb);
    ulonglong2 cyb = ok1 ? *(const ulonglong2*)(gy0 + cb + 4)
                         : make_ulonglong2(0ull, 0ull);
    ull        cyc = ok2 ? *(const ull*)(gy0 + cb + 8) : 0ull;

    int slot = 0;
    for (int ir = 0; ir < nrows; ir++) {
        // ---- prefetch next row (clamped; final iter's values unused) ----
        int rn = r0 + min(ir + 1, nrows - 1);
        const float* gxn = gt   + (size_t)rn * W;
        const float* gyn = pred + (size_t)rn * W;
        ulonglong2 nxa = *(const ulonglong2*)(gxn + cb);
        ulonglong2 nxb = ok1 ? *(const ulonglong2*)(gxn + cb + 4)
                             : make_ulonglong2(0ull, 0ull);
        ull        nxc = ok2 ? *(const ull*)(gxn + cb + 8) : 0ull;
        ulonglong2 nya = *(const ulonglong2*)(gyn + cb);
        ulonglong2 nyb = ok1 ? *(const ulonglong2*)(gyn + cb + 4)
                             : make_ulonglong2(0ull, 0ull);
        ull        nyc = ok2 ? *(const ull*)(gyn + cb + 8) : 0ull;

        // ---- packed elements: s, d, s^2, d^2 for 5 pairs ----
        ull pA0 = F2ADD(cxa.x, cya.x), pA1 = F2ADD(cxa.y, cya.y);
        ull pA2 = F2ADD(cxb.x, cyb.x), pA3 = F2ADD(cxb.y, cyb.y);
        ull pA4 = F2ADD(cxc,   cyc);
        ull pB0 = F2FMA(cya.x, NEG1, cxa.x), pB1 = F2FMA(cya.y, NEG1, cxa.y);
        ull pB2 = F2FMA(cyb.x, NEG1, cxb.x), pB3 = F2FMA(cyb.y, NEG1, cxb.y);
        ull pB4 = F2FMA(cyc,   NEG1, cxc);
        ull pP0 = F2MUL(pA0, pA0), pP1 = F2MUL(pA1, pA1);
        ull pP2 = F2MUL(pA2, pA2), pP3 = F2MUL(pA3, pA3);
        ull pP4 = F2MUL(pA4, pA4);
        ull pQ0 = F2MUL(pB0, pB0), pQ1 = F2MUL(pB1, pB1);
        ull pQ2 = F2MUL(pB2, pB2), pQ3 = F2MUL(pB3, pB3);
        ull pQ4 = F2MUL(pB4, pB4);

        // ---- scalar horizontal 7-tap sums, then pack ----
        ull hA01, hA23, hB01, hB23, hP01, hP23, hQ01, hQ23;
        {
            float e0, e1, e2, e3, e4, e5, e6, e7, e8, e9, h0, h1, h2, h3;
            F2UNPACK(pA0, e0, e1); F2UNPACK(pA1, e2, e3); F2UNPACK(pA2, e4, e5);
            F2UNPACK(pA3, e6, e7); F2UNPACK(pA4, e8, e9);
            h0 = e0 + e1 + e2 + e3 + e4 + e5 + e6;
            h1 = h0 - e0 + e7; h2 = h1 - e1 + e8; h3 = h2 - e2 + e9;
            hA01 = F2PACK(h0, h1); hA23 = F2PACK(h2, h3);
            F2UNPACK(pB0, e0, e1); F2UNPACK(pB1, e2, e3); F2UNPACK(pB2, e4, e5);
            F2UNPACK(pB3, e6, e7); F2UNPACK(pB4, e8, e9);
            h0 = e0 + e1 + e2 + e3 + e4 + e5 + e6;
            h1 = h0 - e0 + e7; h2 = h1 - e1 + e8; h3 = h2 - e2 + e9;
            hB01 = F2PACK(h0, h1); hB23 = F2PACK(h2, h3);
            F2UNPACK(pP0, e0, e1); F2UNPACK(pP1, e2, e3); F2UNPACK(pP2, e4, e5);
            F2UNPACK(pP3, e6, e7); F2UNPACK(pP4, e8, e9);
            h0 = e0 + e1 + e2 + e3 + e4 + e5 + e6;
            h1 = h0 - e0 + e7; h2 = h1 - e1 + e8; h3 = h2 - e2 + e9;
            hP01 = F2PACK(h0, h1); hP23 = F2PACK(h2, h3);
            F2UNPACK(pQ0, e0, e1); F2UNPACK(pQ1, e2, e3); F2UNPACK(pQ2, e4, e5);
            F2UNPACK(pQ3, e6, e7); F2UNPACK(pQ4, e8, e9);
            h0 = e0 + e1 + e2 + e3 + e4 + e5 + e6;
            h1 = h0 - e0 + e7; h2 = h1 - e1 + e8; h3 = h2 - e2 + e9;
            hQ01 = F2PACK(h0, h1); hQ23 = F2PACK(h2, h3);
        }

        // ---- packed vertical sliding window via lane-private ring ----
        ulonglong2 o2, s2;
        o2 = s_ring[0][slot][l];
        vA01 = F2ADD(vA01, F2FMA(o2.x, NEG1, hA01));
        vA23 = F2ADD(vA23, F2FMA(o2.y, NEG1, hA23));
        s2.x = hA01; s2.y = hA23; s_ring[0][slot][l] = s2;
        o2 = s_ring[1][slot][l];
        vB01 = F2ADD(vB01, F2FMA(o2.x, NEG1, hB01));
        vB23 = F2ADD(vB23, F2FMA(o2.y, NEG1, hB23));
        s2.x = hB01; s2.y = hB23; s_ring[1][slot][l] = s2;
        o2 = s_ring[2][slot][l];
        vP01 = F2ADD(vP01, F2FMA(o2.x, NEG1, hP01));
        vP23 = F2ADD(vP23, F2FMA(o2.y, NEG1, hP23));
        s2.x = hP01; s2.y = hP23; s_ring[2][slot][l] = s2;
        o2 = s_ring[3][slot][l];
        vQ01 = F2ADD(vQ01, F2FMA(o2.x, NEG1, hQ01));
        vQ23 = F2ADD(vQ23, F2FMA(o2.y, NEG1, hQ23));
        s2.x = hQ01; s2.y = hQ23; s_ring[3][slot][l] = s2;
        slot = (slot == 6) ? 0 : slot + 1;

        if (ir >= 6) {
            // ---- MSE over this lane's own 4 columns (tiled exactly once) ----
            macc = F2ADD(macc, pQ0);
            macc = F2ADD(macc, pQ1);

            // ---- packed SSIM evaluation, 2 windows per op ----
            #pragma unroll
            for (int m = 0; m < 2; m++) {
                ull A = m ? vA23 : vA01, B = m ? vB23 : vB01;
                ull P = m ? vP23 : vP01, Q = m ? vQ23 : vQ01;
                ull A2 = F2MUL(A, A);
                ull B2 = F2MUL(B, B);
                ull U  = F2FMA(B2, NEG1, A2);   // A2-B2
                ull V  = F2ADD(A2, B2);
                ull n1 = F2ADD(U, C1a2);
                ull d1 = F2ADD(V, C1a2);
                ull PM = F2FMA(Q, NEG1, P);     // P-Q
                ull PP = F2ADD(P, Q);
                ull nU = F2FMA(A2, NEG1, B2);   // -(A2-B2)
                ull n2 = F2FMA(TC2, F2FMA(K49, PM, nU), C2a2);
                ull nV = F2MUL(V, NEG1);
                ull d2 = F2FMA(TC2, F2FMA(K49, PP, nV), C2a2);
                ull NN = F2MUL(n1, n2);
                ull DD = F2MUL(d1, d2);
                float nn0, nn1, dd0, dd1;
                F2UNPACK(NN, nn0, nn1);
                F2UNPACK(DD, dd0, dd1);
                int j0 = 2 * m;
                if (cb + j0     < OUTW) acc += __fdividef(nn0, dd0);
                if (cb + j0 + 1 < OUTW) acc += __fdividef(nn1, dd1);
            }
        }

        // rotate pipeline registers
        cxa = nxa; cxb = nxb; cxc = nxc;
        cya = nya; cyb = nyb; cyc = nyc;
    }

    // warp reduction + atomics + fused finalize in the last block
    float m0, m1; F2UNPACK(macc, m0, m1);
    float msel = m0 + m1;
    #pragma unroll
    for (int o = 16; o > 0; o >>= 1) {
        acc  += __shfl_down_sync(0xffffffffu, acc, o);
        msel += __shfl_down_sync(0xffffffffu, msel, o);
    }
    if (l == 0) {
        atomicAdd(&g_ssim_sum, (double)acc);
        atomicAdd(&g_mse_sum,  (double)msel);
        __threadfence();
        unsigned int ticket = atomicAdd(&g_done, 1u);
        if (ticket == NBLK - 1) {
            __threadfence();
            double mse   = g_mse_sum  / ((double)W * (double)H);
            double mssim = g_ssim_sum / ((double)OUTW * (double)OUTH);
            out[0] = (float)(mse * exp(1.0 - mssim));
            // reset scratch for the next graph replay
            g_mse_sum  = 0.0;
            g_ssim_sum = 0.0;
            g_min =  1e30f;
            g_max = -1e30f;
            g_done = 0u;
        }
    }
}

// ---------------- launcher ----------------
extern "C" void kernel_launch(void* const* d_in, const int* in_sizes, int n_in,
                              void* d_out, int out_size)
{
    const float* pred = (const float*)d_in[0];   // depth_pred
    const float* gt   = (const float*)d_in[1];   // depth_gt

    int n4 = (W * H) / 4;
    reduce_kernel<<<2368, 256>>>((const float4*)pred, (const float4*)gt, n4);

    dim3 grid(NSTRIP, GY);   // (32, 70), one warp per block
    ssim_kernel<<<grid, 32>>>(pred, gt, (float*)d_out);
}

// round 9
// speedup vs baseline: 2.7597x; 1.0014x over previous
#include <cuda_runtime.h>
#include <math.h>
#include <stdint.h>

typedef unsigned long long ull;

// Problem constants (4096 x 4096 fp32 images, 7x7 SSIM window)
#define W     4096
#define H     4096
#define OUTW  4090      // W - 6 (VALID 7x7)
#define OUTH  4090

#define STRIPW 128      // output columns per warp (32 lanes x 4 cols)
#define NSTRIP 32       // ceil(4090/128)
#define RH     59       // output rows per block strip
#define GY     70       // ceil(4090/59)
#define NBLK   (NSTRIP * GY)   // 2240 ssim blocks (~15.1 per SM, smem-cap fill)

// ---------------- device scratch (statically initialized; the last ssim
// block resets everything so each graph replay starts clean) ---------------
__device__ double g_mse_sum  = 0.0;
__device__ double g_ssim_sum = 0.0;
__device__ float  g_min =  1e30f;
__device__ float  g_max = -1e30f;
__device__ unsigned int g_done = 0;

__device__ __forceinline__ void atomicMaxF(float* a, float v) {
    if (v >= 0.f) atomicMax((int*)a, __float_as_int(v));
    else          atomicMin((unsigned int*)a, __float_as_uint(v));
}
__device__ __forceinline__ void atomicMinF(float* a, float v) {
    if (v >= 0.f) atomicMin((int*)a, __float_as_int(v));
    else          atomicMax((unsigned int*)a, __float_as_uint(v));
}

// ---------------- packed f32x2 helpers (sm_100a) ----------------
__device__ __forceinline__ ull F2ADD(ull a, ull b) {
    ull r; asm("add.rn.f32x2 %0,%1,%2;" : "=l"(r) : "l"(a), "l"(b)); return r;
}
__device__ __forceinline__ ull F2MUL(ull a, ull b) {
    ull r; asm("mul.rn.f32x2 %0,%1,%2;" : "=l"(r) : "l"(a), "l"(b)); return r;
}
__device__ __forceinline__ ull F2FMA(ull a, ull b, ull c) {
    ull r; asm("fma.rn.f32x2 %0,%1,%2,%3;" : "=l"(r) : "l"(a), "l"(b), "l"(c)); return r;
}
__device__ __forceinline__ ull F2PACK(float lo, float hi) {
    ull r; asm("mov.b64 %0,{%1,%2};" : "=l"(r) : "f"(lo), "f"(hi)); return r;
}
__device__ __forceinline__ void F2UNPACK(ull a, float& lo, float& hi) {
    asm("mov.b64 {%0,%1},%2;" : "=f"(lo), "=f"(hi) : "l"(a));
}

// ---------------- pass 1: min/max of pred + MSE of rows 0..5 ----------------
// (MSE of rows >= 6 is accumulated inside the ssim kernel, which tiles those
//  rows exactly once across strips.)
#define MSE_ROWS4 ((6 * W) / 4)   // first 6 rows in float4 units

__global__ __launch_bounds__(256) void reduce_kernel(
    const float4* __restrict__ pred, const float4* __restrict__ gt, int n4)
{
    float mse = 0.f;
    float mn  = 1e30f;
    float mx  = -1e30f;

    for (int i = blockIdx.x * blockDim.x + threadIdx.x; i < n4;
         i += gridDim.x * blockDim.x) {
        float4 p = pred[i];
        mn = fminf(mn, fminf(fminf(p.x, p.y), fminf(p.z, p.w)));
        mx = fmaxf(mx, fmaxf(fmaxf(p.x, p.y), fmaxf(p.z, p.w)));
        if (i < MSE_ROWS4) {
            float4 g = gt[i];
            float d0 = p.x - g.x, d1 = p.y - g.y, d2 = p.z - g.z, d3 = p.w - g.w;
            mse = fmaf(d0, d0, mse);
            mse = fmaf(d1, d1, mse);
            mse = fmaf(d2, d2, mse);
            mse = fmaf(d3, d3, mse);
        }
    }
    #pragma unroll
    for (int o = 16; o > 0; o >>= 1) {
        mse += __shfl_down_sync(0xffffffffu, mse, o);
        mn = fminf(mn, __shfl_down_sync(0xffffffffu, mn, o));
        mx = fmaxf(mx, __shfl_down_sync(0xffffffffu, mx, o));
    }
    __shared__ float smse[8], smn[8], smx[8];
    int lane = threadIdx.x & 31, wid = threadIdx.x >> 5;
    if (lane == 0) { smse[wid] = mse; smn[wid] = mn; smx[wid] = mx; }
    __syncthreads();
    if (threadIdx.x < 8) {
        float a = smse[threadIdx.x];
        float b = smn[threadIdx.x];
        float c = smx[threadIdx.x];
        #pragma unroll
        for (int o = 4; o > 0; o >>= 1) {
            a += __shfl_down_sync(0xffu, a, o);
            b = fminf(b, __shfl_down_sync(0xffu, b, o));
            c = fmaxf(c, __shfl_down_sync(0xffu, c, o));
        }
        if (threadIdx.x == 0) {
            if (a != 0.f) atomicAdd(&g_mse_sum, (double)a);
            atomicMinF(&g_min, b);
            atomicMaxF(&g_max, c);
        }
    }
}

// ---------------- pass 2: SSIM map sum + MSE tail + fused finalize --------
// Sum/difference decomposition: s = x+y, d = x-y. Window sums
//   A = sum(s), B = sum(d), P = sum(s^2), Q = sum(d^2)
// give (rescaled so num/den scale factors cancel):
//   num1 = A^2-B^2 + C1a        den1 = A^2+B^2 + C1a
//   num2 = TC*(49(P-Q)-(A^2-B^2)) + C2a
//   den2 = TC*(49(P+Q)-(A^2+B^2)) + C2a
// with TC = 2*49/48, C1a = 2*2401*(K1*R)^2, C2a = 4*2401*(K2*R)^2.
// One warp per block; no barriers; packed f32x2 for element, vertical and
// evaluation stages; scalar horizontal 7-tap.

__global__ __launch_bounds__(32) void ssim_kernel(
    const float* __restrict__ pred, const float* __restrict__ gt, float* __restrict__ out)
{
    __shared__ ulonglong2 s_ring[4][7][32];   // vertical 7-row ring, lane-private

    const int l  = threadIdx.x;
    const int c0 = blockIdx.x * STRIPW;
    const int r0 = blockIdx.y * RH;
    const int chunk_rows = min(RH, OUTH - r0);
    const int nrows = chunk_rows + 6;

    const float rng = g_max - g_min;
    float k1 = 0.01f * rng, k2 = 0.03f * rng;
    const float C1a = 2.f * 2401.f * k1 * k1;
    const float C2a = 4.f * 2401.f * k2 * k2;

    const ull C1a2 = F2PACK(C1a, C1a);
    const ull C2a2 = F2PACK(C2a, C2a);
    const ull K49  = F2PACK(49.f, 49.f);
    const ull TC2  = F2PACK(49.f / 24.f, 49.f / 24.f);
    const ull NEG1 = F2PACK(-1.f, -1.f);

    const int cb = c0 + 4 * l;                // first input col of this lane
    const bool ok1 = (cb + 7) < W;            // 2nd float4 in range
    const bool ok2 = (cb + 9) < W;            // trailing float2 in range

    #pragma unroll
    for (int sct = 0; sct < 7; sct++) {
        ulonglong2 z2; z2.x = 0ull; z2.y = 0ull;
        s_ring[0][sct][l] = z2; s_ring[1][sct][l] = z2;
        s_ring[2][sct][l] = z2; s_ring[3][sct][l] = z2;
    }

    ull vA01 = 0, vA23 = 0, vB01 = 0, vB23 = 0;
    ull vP01 = 0, vP23 = 0, vQ01 = 0, vQ23 = 0;
    ull macc = 0;                              // packed MSE accumulator
    float acc = 0.f;

    // prime the pipeline: load row r0 (pairs directly as ull)
    const float* gx0 = gt   + (size_t)r0 * W;
    const float* gy0 = pred + (size_t)r0 * W;
    ulonglong2 cxa = *(const ulonglong2*)(gx0 + cb);                 // cols 0..3
    ulonglong2 cxb = ok1 ? *(const ulonglong2*)(gx0 + cb + 4)
                         : make_ulonglong2(0ull, 0ull);              // cols 4..7
    ull        cxc = ok2 ? *(const ull*)(gx0 + cb + 8) : 0ull;       // cols 8..9
    ulonglong2 cya = *(const ulonglong2*)(gy0 + cb);
    ulonglong2 cyb = ok1 ? *(const ulonglong2*)(gy0 + cb + 4)
                         : make_ulonglong2(0ull, 0ull);
    ull        cyc = ok2 ? *(const ull*)(gy0 + cb + 8) : 0ull;

    int slot = 0;
    for (int ir = 0; ir < nrows; ir++) {
        // ---- prefetch next row (clamped; final iter's values unused) ----
        int rn = r0 + min(ir + 1, nrows - 1);
        const float* gxn = gt   + (size_t)rn * W;
        const float* gyn = pred + (size_t)rn * W;
        ulonglong2 nxa = *(const ulonglong2*)(gxn + cb);
        ulonglong2 nxb = ok1 ? *(const ulonglong2*)(gxn + cb + 4)
                             : make_ulonglong2(0ull, 0ull);
        ull        nxc = ok2 ? *(const ull*)(gxn + cb + 8) : 0ull;
        ulonglong2 nya = *(const ulonglong2*)(gyn + cb);
        ulonglong2 nyb = ok1 ? *(const ulonglong2*)(gyn + cb + 4)
                             : make_ulonglong2(0ull, 0ull);
        ull        nyc = ok2 ? *(const ull*)(gyn + cb + 8) : 0ull;

        // ---- packed elements: s, d, s^2, d^2 for 5 pairs ----
        ull pA0 = F2ADD(cxa.x, cya.x), pA1 = F2ADD(cxa.y, cya.y);
        ull pA2 = F2ADD(cxb.x, cyb.x), pA3 = F2ADD(cxb.y, cyb.y);
        ull pA4 = F2ADD(cxc,   cyc);
        ull pB0 = F2FMA(cya.x, NEG1, cxa.x), pB1 = F2FMA(cya.y, NEG1, cxa.y);
        ull pB2 = F2FMA(cyb.x, NEG1, cxb.x), pB3 = F2FMA(cyb.y, NEG1, cxb.y);
        ull pB4 = F2FMA(cyc,   NEG1, cxc);
        ull pP0 = F2MUL(pA0, pA0), pP1 = F2MUL(pA1, pA1);
        ull pP2 = F2MUL(pA2, pA2), pP3 = F2MUL(pA3, pA3);
        ull pP4 = F2MUL(pA4, pA4);
        ull pQ0 = F2MUL(pB0, pB0), pQ1 = F2MUL(pB1, pB1);
        ull pQ2 = F2MUL(pB2, pB2), pQ3 = F2MUL(pB3, pB3);
        ull pQ4 = F2MUL(pB4, pB4);

        // ---- scalar horizontal 7-tap sums, then pack ----
        ull hA01, hA23, hB01, hB23, hP01, hP23, hQ01, hQ23;
        {
            float e0, e1, e2, e3, e4, e5, e6, e7, e8, e9, h0, h1, h2, h3;
            F2UNPACK(pA0, e0, e1); F2UNPACK(pA1, e2, e3); F2UNPACK(pA2, e4, e5);
            F2UNPACK(pA3, e6, e7); F2UNPACK(pA4, e8, e9);
            h0 = e0 + e1 + e2 + e3 + e4 + e5 + e6;
            h1 = h0 - e0 + e7; h2 = h1 - e1 + e8; h3 = h2 - e2 + e9;
            hA01 = F2PACK(h0, h1); hA23 = F2PACK(h2, h3);
            F2UNPACK(pB0, e0, e1); F2UNPACK(pB1, e2, e3); F2UNPACK(pB2, e4, e5);
            F2UNPACK(pB3, e6, e7); F2UNPACK(pB4, e8, e9);
            h0 = e0 + e1 + e2 + e3 + e4 + e5 + e6;
            h1 = h0 - e0 + e7; h2 = h1 - e1 + e8; h3 = h2 - e2 + e9;
            hB01 = F2PACK(h0, h1); hB23 = F2PACK(h2, h3);
            F2UNPACK(pP0, e0, e1); F2UNPACK(pP1, e2, e3); F2UNPACK(pP2, e4, e5);
            F2UNPACK(pP3, e6, e7); F2UNPACK(pP4, e8, e9);
            h0 = e0 + e1 + e2 + e3 + e4 + e5 + e6;
            h1 = h0 - e0 + e7; h2 = h1 - e1 + e8; h3 = h2 - e2 + e9;
            hP01 = F2PACK(h0, h1); hP23 = F2PACK(h2, h3);
            F2UNPACK(pQ0, e0, e1); F2UNPACK(pQ1, e2, e3); F2UNPACK(pQ2, e4, e5);
            F2UNPACK(pQ3, e6, e7); F2UNPACK(pQ4, e8, e9);
            h0 = e0 + e1 + e2 + e3 + e4 + e5 + e6;
            h1 = h0 - e0 + e7; h2 = h1 - e1 + e8; h3 = h2 - e2 + e9;
            hQ01 = F2PACK(h0, h1); hQ23 = F2PACK(h2, h3);
        }

        // ---- packed vertical sliding window via lane-private ring ----
        ulonglong2 o2, s2;
        o2 = s_ring[0][slot][l];
        vA01 = F2ADD(vA01, F2FMA(o2.x, NEG1, hA01));
        vA23 = F2ADD(vA23, F2FMA(o2.y, NEG1, hA23));
        s2.x = hA01; s2.y = hA23; s_ring[0][slot][l] = s2;
        o2 = s_ring[1][slot][l];
        vB01 = F2ADD(vB01, F2FMA(o2.x, NEG1, hB01));
        vB23 = F2ADD(vB23, F2FMA(o2.y, NEG1, hB23));
        s2.x = hB01; s2.y = hB23; s_ring[1][slot][l] = s2;
        o2 = s_ring[2][slot][l];
        vP01 = F2ADD(vP01, F2FMA(o2.x, NEG1, hP01));
        vP23 = F2ADD(vP23, F2FMA(o2.y, NEG1, hP23));
        s2.x = hP01; s2.y = hP23; s_ring[2][slot][l] = s2;
        o2 = s_ring[3][slot][l];
        vQ01 = F2ADD(vQ01, F2FMA(o2.x, NEG1, hQ01));
        vQ23 = F2ADD(vQ23, F2FMA(o2.y, NEG1, hQ23));
        s2.x = hQ01; s2.y = hQ23; s_ring[3][slot][l] = s2;
        slot = (slot == 6) ? 0 : slot + 1;

        if (ir >= 6) {
            // ---- MSE over this lane's own 4 columns (tiled exactly once) ----
            macc = F2ADD(macc, pQ0);
            macc = F2ADD(macc, pQ1);

            // ---- packed SSIM evaluation, 2 windows per op ----
            #pragma unroll
            for (int m = 0; m < 2; m++) {
                ull A = m ? vA23 : vA01, B = m ? vB23 : vB01;
                ull P = m ? vP23 : vP01, Q = m ? vQ23 : vQ01;
                ull A2 = F2MUL(A, A);
                ull B2 = F2MUL(B, B);
                ull U  = F2FMA(B2, NEG1, A2);   // A2-B2
                ull V  = F2ADD(A2, B2);
                ull n1 = F2ADD(U, C1a2);
                ull d1 = F2ADD(V, C1a2);
                ull PM = F2FMA(Q, NEG1, P);     // P-Q
                ull PP = F2ADD(P, Q);
                ull nU = F2FMA(A2, NEG1, B2);   // -(A2-B2)
                ull n2 = F2FMA(TC2, F2FMA(K49, PM, nU), C2a2);
                ull nV = F2MUL(V, NEG1);
                ull d2 = F2FMA(TC2, F2FMA(K49, PP, nV), C2a2);
                ull NN = F2MUL(n1, n2);
                ull DD = F2MUL(d1, d2);
                float nn0, nn1, dd0, dd1;
                F2UNPACK(NN, nn0, nn1);
                F2UNPACK(DD, dd0, dd1);
                int j0 = 2 * m;
                if (cb + j0     < OUTW) acc += __fdividef(nn0, dd0);
                if (cb + j0 + 1 < OUTW) acc += __fdividef(nn1, dd1);
            }
        }

        // rotate pipeline registers
        cxa = nxa; cxb = nxb; cxc = nxc;
        cya = nya; cyb = nyb; cyc = nyc;
    }

    // warp reduction + atomics + fused finalize in the last block
    float m0, m1; F2UNPACK(macc, m0, m1);
    float msel = m0 + m1;
    #pragma unroll
    for (int o = 16; o > 0; o >>= 1) {
        acc  += __shfl_down_sync(0xffffffffu, acc, o);
        msel += __shfl_down_sync(0xffffffffu, msel, o);
    }
    if (l == 0) {
        atomicAdd(&g_ssim_sum, (double)acc);
        atomicAdd(&g_mse_sum,  (double)msel);
        __threadfence();
        unsigned int ticket = atomicAdd(&g_done, 1u);
        if (ticket == NBLK - 1) {
            __threadfence();
            double mse   = g_mse_sum  / ((double)W * (double)H);
            double mssim = g_ssim_sum / ((double)OUTW * (double)OUTH);
            out[0] = (float)(mse * exp(1.0 - mssim));
            // reset scratch for the next graph replay
            g_mse_sum  = 0.0;
            g_ssim_sum = 0.0;
            g_min =  1e30f;
            g_max = -1e30f;
            g_done = 0u;
        }
    }
}

// ---------------- launcher ----------------
extern "C" void kernel_launch(void* const* d_in, const int* in_sizes, int n_in,
                              void* d_out, int out_size)
{
    const float* pred = (const float*)d_in[0];   // depth_pred
    const float* gt   = (const float*)d_in[1];   // depth_gt

    int n4 = (W * H) / 4;
    reduce_kernel<<<2368, 256>>>((const float4*)pred, (const float4*)gt, n4);

    dim3 grid(NSTRIP, GY);   // (32, 70), one warp per block
    ssim_kernel<<<grid, 32>>>(pred, gt, (float*)d_out);
}